// round 14
// baseline (speedup 1.0000x reference)
#include <cuda_runtime.h>
#include <cuda_fp16.h>

typedef unsigned int u32;
typedef unsigned short u16;

#define NFEAT 256
#define NPB   128          // nodes per tile (m16 per warp)
#define NTHR  256

// ---- smem layout (bytes) ----
#define W_STRIDE 528                        // 64 rows x (512B + 16B pad): ldmatrix conflict-free
#define OFF_WH   0
#define OFF_X    33792                      // X ring: 4 stages x (8 warps x 16 rows x 64B)
#define XSTAGE   8192
#define NSTAGE   4
#define OFF_FC   (OFF_X + NSTAGE * XSTAGE)  // 66560
#define FCQ   0
#define FW2   512
#define FB1   544
#define FBZ   576
#define FBH   608
#define FB2   640
#define SMEM_BYTES (OFF_FC + 642 * 4)       // 69128 -> 3 CTAs/SM

// W folded: [n=64][k=256] row-major fp16
__device__ __align__(16) u16 g_Wh[64 * 256];
// fc1 packed for B-fragments: fc1q[jp][i] = {lo: fc1[2jp][i], hi: fc1[2jp+1][i]} fp16
__device__ __align__(16) u32 g_fc1q[16 * 32];

// ---------------------------------------------------------------------------
// Prep: fold wc[j][k] = (wz[0]+wz[1]) | (wh[0]+wh[1]) (x-rows only; h0=0 kills
// the H half of the concat and the r-gate). Also pack fc1 into b-frag layout.
// ---------------------------------------------------------------------------
__global__ void prep_kernel(const float* __restrict__ wz, const float* __restrict__ wh,
                            const float* __restrict__ fc1w) {
    int idx = blockIdx.x * 256 + threadIdx.x;
    if (idx < 64 * 256) {
        int j = idx >> 8, k = idx & 255;
        const int D1 = 288 * 32;
        float wc = (j < 32) ? (wz[k * 32 + j] + wz[D1 + k * 32 + j])
                            : (wh[k * 32 + (j - 32)] + wh[D1 + k * 32 + (j - 32)]);
        __half h = __float2half_rn(wc);
        g_Wh[j * 256 + k] = *reinterpret_cast<u16*>(&h);
    }
    if (idx < 512) {
        int jp = idx >> 5, i = idx & 31;
        __half lo = __float2half_rn(fc1w[(2 * jp) * 32 + i]);
        __half hi = __float2half_rn(fc1w[(2 * jp + 1) * 32 + i]);
        g_fc1q[idx] = ((u32)*reinterpret_cast<u16*>(&hi) << 16) | *reinterpret_cast<u16*>(&lo);
    }
}

// ---------------------------------------------------------------------------
// helpers
// ---------------------------------------------------------------------------
__device__ __forceinline__ u32 s2u(const void* p) {
    u32 a;
    asm("{ .reg .u64 t; cvta.to.shared.u64 t, %1; cvt.u32.u64 %0, t; }" : "=r"(a) : "l"(p));
    return a;
}
__device__ __forceinline__ void ldsm4(u32 a, u32& r0, u32& r1, u32& r2, u32& r3) {
    asm volatile("ldmatrix.sync.aligned.m8n8.x4.shared.b16 {%0,%1,%2,%3}, [%4];"
                 : "=r"(r0), "=r"(r1), "=r"(r2), "=r"(r3) : "r"(a));
}
__device__ __forceinline__ void mma16816(float* c, const u32* a, u32 b0, u32 b1) {
    asm volatile("mma.sync.aligned.m16n8k16.row.col.f32.f16.f16.f32 "
                 "{%0,%1,%2,%3},{%4,%5,%6,%7},{%8,%9},{%0,%1,%2,%3};"
                 : "+f"(c[0]), "+f"(c[1]), "+f"(c[2]), "+f"(c[3])
                 : "r"(a[0]), "r"(a[1]), "r"(a[2]), "r"(a[3]), "r"(b0), "r"(b1));
}
__device__ __forceinline__ u32 packh(float lo, float hi) {  // reg = {hi16 | lo16}
    u32 r; asm("cvt.rn.f16x2.f32 %0, %1, %2;" : "=r"(r) : "f"(hi), "f"(lo)); return r;
}
__device__ __forceinline__ void cpasync16(u32 dst, const void* src) {
    asm volatile("cp.async.cg.shared.global [%0], [%1], 16;" :: "r"(dst), "l"(src));
}
__device__ __forceinline__ void cp_commit() {
    asm volatile("cp.async.commit_group;" ::: "memory");
}
__device__ __forceinline__ void cp_wait3() {
    asm volatile("cp.async.wait_group 3;" ::: "memory");
}
__device__ __forceinline__ void l2_prefetch(const void* p) {
    asm volatile("prefetch.global.L2 [%0];" :: "l"(p));
}
__device__ __forceinline__ float sigf(float x) { return 1.f / (1.f + __expf(-x)); }
__device__ __forceinline__ float tanhg(float x) {
    float e = __expf(-2.f * fabsf(x));
    return copysignf((1.f - e) / (1.f + e), x);
}
__device__ __forceinline__ float2 lds64(u32 a) {
    float2 v;
    asm volatile("ld.shared.v2.f32 {%0,%1}, [%2];" : "=f"(v.x), "=f"(v.y) : "r"(a));
    return v;
}

// ---------------------------------------------------------------------------
// Persistent fused kernel, 3 CTAs/SM. Next tile is streamed SEQUENTIALLY into
// L2 via prefetch.global.L2 (DRAM row-buffer friendly); the XOR-swizzled
// 4-deep cp.async ring then consumes column-chunks out of L2. A-fragment
// fetch pipelined one chunk ahead; pipeline flows across tiles. fp16 HMMA
// GEMM + register-resident GRU gates + tensor-core fc head.
// ---------------------------------------------------------------------------
__global__ void __launch_bounds__(NTHR, 3)
fused_kernel(const float* __restrict__ x,
             const float* __restrict__ bz, const float* __restrict__ bh,
             const float* __restrict__ fc1b,
             const float* __restrict__ fc2w, const float* __restrict__ fc2b,
             float* __restrict__ out, int n, int ntiles)
{
    extern __shared__ char sm[];
    const u32 sb = s2u(sm);
    const int tid  = threadIdx.x;
    const int wid  = tid >> 5;
    const int lane = tid & 31;
    const int g    = lane >> 2;        // row within 8-row group
    const int tg   = lane & 3;
    const int gs   = gridDim.x;
    const int s    = g & 3;            // swizzle key

    // cp.async write: lane (g,tg) writes its 16B unit tg at swizzled slot tg^s
    const u32 xw = sb + OFF_X + (u32)wid * 1024 + (u32)g * 64 + (u32)((tg ^ s) << 4);
    // fragment reads (LDS.64) at swizzled addresses (validated R10-R13)
    const u32 ra0 = sb + OFF_X + (u32)wid * 1024 + (u32)g * 64
                  + (u32)((((tg >> 1) ^ s) << 4) + ((tg & 1) << 3));
    const u32 ra2 = sb + OFF_X + (u32)wid * 1024 + (u32)g * 64
                  + (u32)(((((tg >> 1) | 2) ^ s) << 4) + ((tg & 1) << 3));

    // per-tile source row pointers (rows g, g+8 of this warp's m16 slice), clamped
    const float* psC[2];
    auto mk_ps = [&](int tile) {
        #pragma unroll
        for (int q = 0; q < 2; q++) {
            int node = tile * NPB + wid * 16 + q * 8 + g;
            if (node > n - 1) node = n - 1;
            psC[q] = x + (size_t)node * NFEAT + tg * 4;
        }
    };
    const size_t tileStride = (size_t)gs * NPB * NFEAT;   // floats between my tiles
    const float* const pfMax = x + ((size_t)n * NFEAT - 32);  // prefetch clamp

    int t = blockIdx.x;
    mk_ps(t);

    // ---- preamble: chunks 0..3 of first tile into stages 0..3 ----
    #pragma unroll
    for (int c = 0; c < NSTAGE; c++) {
        cpasync16(xw + c * XSTAGE,       psC[0] + c * 16);
        cpasync16(xw + c * XSTAGE + 512, psC[1] + c * 16);
        cp_commit();
    }

    // ---- stage W into padded smem (once) ----
    {
        const uint4* sH = (const uint4*)g_Wh;
        #pragma unroll
        for (int it = 0; it < 8; it++) {
            int e = tid + 256 * it;
            int row = e >> 5, c16 = e & 31;
            *(uint4*)(sm + OFF_WH + row * W_STRIDE + c16 * 16) = sH[e];
        }
    }
    // ---- stage fc head + biases (once) ----
    u32* FCq = (u32*)(sm + OFF_FC);
    float* FCf = (float*)(sm + OFF_FC);
    FCq[FCQ + tid] = g_fc1q[tid];
    FCq[FCQ + 256 + tid] = g_fc1q[256 + tid];
    if (tid < 32) {
        FCf[FW2 + tid] = fc2w[tid];
        FCf[FB1 + tid] = fc1b[tid];
        FCf[FBZ + tid] = bz[tid];
        FCf[FBH + tid] = bh[tid];
    }
    if (tid == 0) FCf[FB2] = fc2b[0];

    // ldmatrix address for B (n16 x k16, x4), validated R3-R13
    const int rowB = (lane & 7) + ((lane >> 4) & 1) * 8;
    const u32 boff = (u32)rowB * W_STRIDE + (u32)((lane >> 3) & 1) * 16;

    // ---- pipeline setup: fetch chunk 0 fragments into A_cur ----
    u32 A_cur[4];
    cp_wait3();                // 4 preamble commits -> chunk 0 landed
    __syncwarp();
    {
        float2 d0 = lds64(ra0);
        float2 d1 = lds64(ra0 + 512);
        float2 d2 = lds64(ra2);
        float2 d3 = lds64(ra2 + 512);
        A_cur[0] = packh(d0.x, d0.y);
        A_cur[1] = packh(d1.x, d1.y);
        A_cur[2] = packh(d2.x, d2.y);
        A_cur[3] = packh(d3.x, d3.y);
    }

    __syncthreads();   // W/FC staged; the only CTA barrier

    // =========================== persistent tile loop ===========================
    while (t < ntiles) {
        const int tn = t + gs;
        const bool hasNext = (tn < ntiles);

        // ---- stream NEXT tile sequentially into L2 (DRAM-friendly order) ----
        // 1024 x 128B lines per tile; warp w covers lines [w*32*4 ..) in
        // 4KB-contiguous runs per prefetch step.
        if (hasNext) {
            const float* nb = x + (size_t)tn * NPB * NFEAT;
            #pragma unroll
            for (int q = 0; q < 4; q++) {
                const float* pa = nb + ((size_t)(tid + 256 * q)) * 32;   // 128B line
                if (pa > pfMax) pa = pfMax;
                l2_prefetch(pa);
            }
        }

        float acc[8][4];
        #pragma unroll
        for (int nt = 0; nt < 8; nt++)
            #pragma unroll
            for (int r = 0; r < 4; r++) acc[nt][r] = 0.f;

        #pragma unroll
        for (int c = 0; c < 16; c++) {
            const int st = c & (NSTAGE - 1);

            // refill stage st: chunks 4..15 of this tile (iters 0..11), then
            // chunks 0..3 of my NEXT tile (iters 12..15, psC advanced in place)
            if (c == 12) {
                if (hasNext) {
                    if ((tn + 1) * NPB <= n) {        // fast path: no clamping
                        psC[0] += tileStride;
                        psC[1] += tileStride;
                    } else {
                        mk_ps(tn);                    // final partial tile
                    }
                }
            }
            if (c < 12) {
                cpasync16(xw + st * XSTAGE,       psC[0] + (c + 4) * 16);
                cpasync16(xw + st * XSTAGE + 512, psC[1] + (c + 4) * 16);
            } else if (hasNext) {
                cpasync16(xw + st * XSTAGE,       psC[0] + (c - 12) * 16);
                cpasync16(xw + st * XSTAGE + 512, psC[1] + (c - 12) * 16);
            }
            cp_commit();       // uniform group counting (empty groups OK)

            // B fragments + 8 HMMAs on the prefetched A_cur (chunk c)
            const u32 kb = (u32)c * 32;
            #pragma unroll
            for (int nq = 0; nq < 4; nq++) {
                u32 b0, b1, b2, b3;
                ldsm4(sb + OFF_WH + boff + nq * 16 * W_STRIDE + kb, b0, b1, b2, b3);
                mma16816(acc[2 * nq],     A_cur, b0, b1);
                mma16816(acc[2 * nq + 1], A_cur, b2, b3);
            }

            // fetch chunk c+1 fragments (c==15: next tile's chunk 0) for next iter
            cp_wait3();        // groups 0..c+1 complete
            __syncwarp();
            const int stn = (c + 1) & (NSTAGE - 1);
            float2 d0 = lds64(ra0 + stn * XSTAGE);
            float2 d1 = lds64(ra0 + stn * XSTAGE + 512);
            float2 d2 = lds64(ra2 + stn * XSTAGE);
            float2 d3 = lds64(ra2 + stn * XSTAGE + 512);
            A_cur[0] = packh(d0.x, d0.y);
            A_cur[1] = packh(d1.x, d1.y);
            A_cur[2] = packh(d2.x, d2.y);
            A_cur[3] = packh(d3.x, d3.y);
        }

        // ============== register-resident epilogue (R6-R13, proven) ==============
        u32 Afc[2][4];
        #pragma unroll
        for (int c = 0; c < 2; c++)
            #pragma unroll
            for (int half = 0; half < 2; half++) {
                int ntz = 2 * c + half;
                float2 bzv = *(float2*)(FCf + FBZ + 8 * ntz + 2 * tg);
                float2 bhv = *(float2*)(FCf + FBH + 8 * ntz + 2 * tg);
                float h0 = (1.f - sigf(acc[ntz][0] + bzv.x)) * tanhg(acc[ntz + 4][0] + bhv.x);
                float h1 = (1.f - sigf(acc[ntz][1] + bzv.y)) * tanhg(acc[ntz + 4][1] + bhv.y);
                float h2 = (1.f - sigf(acc[ntz][2] + bzv.x)) * tanhg(acc[ntz + 4][2] + bhv.x);
                float h3 = (1.f - sigf(acc[ntz][3] + bzv.y)) * tanhg(acc[ntz + 4][3] + bhv.y);
                Afc[c][half * 2 + 0] = packh(h0, h1);
                Afc[c][half * 2 + 1] = packh(h2, h3);
            }

        float a2[4][4];
        #pragma unroll
        for (int q = 0; q < 4; q++) {
            float2 b1v = *(float2*)(FCf + FB1 + 8 * q + 2 * tg);
            a2[q][0] = b1v.x; a2[q][1] = b1v.y;
            a2[q][2] = b1v.x; a2[q][3] = b1v.y;
        }
        #pragma unroll
        for (int c = 0; c < 2; c++)
            #pragma unroll
            for (int q = 0; q < 4; q++) {
                u32 bf0 = FCq[FCQ + (tg + 8 * c) * 32 + g + 8 * q];
                u32 bf1 = FCq[FCQ + (tg + 4 + 8 * c) * 32 + g + 8 * q];
                mma16816(a2[q], Afc[c], bf0, bf1);
            }

        const float b2 = FCf[FB2];
        {
            float og = 0.f, og8 = 0.f;
            #pragma unroll
            for (int q = 0; q < 4; q++) {
                float2 w2 = *(float2*)(FCf + FW2 + 8 * q + 2 * tg);
                og  = fmaf(fmaxf(a2[q][0], 0.f), w2.x, og);
                og  = fmaf(fmaxf(a2[q][1], 0.f), w2.y, og);
                og8 = fmaf(fmaxf(a2[q][2], 0.f), w2.x, og8);
                og8 = fmaf(fmaxf(a2[q][3], 0.f), w2.y, og8);
            }
            og  += __shfl_xor_sync(0xffffffffu, og, 1);
            og  += __shfl_xor_sync(0xffffffffu, og, 2);
            og8 += __shfl_xor_sync(0xffffffffu, og8, 1);
            og8 += __shfl_xor_sync(0xffffffffu, og8, 2);
            if (tg == 0) {
                int node = t * NPB + wid * 16 + g;
                if (node < n)     out[node]     = sigf(og + b2);
                if (node + 8 < n) out[node + 8] = sigf(og8 + b2);
            }
        }

        t = tn;
    }
}

// ---------------------------------------------------------------------------
// Launch. Inputs: x, edge_index(dead), w_z, b_z, w_r(dead), b_r(dead),
// w_h, b_h, fc1_w, fc1_b, fc2_w, fc2_b. Output: [N,1] float.
// ---------------------------------------------------------------------------
extern "C" void kernel_launch(void* const* d_in, const int* in_sizes, int n_in,
                              void* d_out, int out_size) {
    const float* x    = (const float*)d_in[0];
    const float* wz   = (const float*)d_in[2];
    const float* bz   = (const float*)d_in[3];
    const float* wh   = (const float*)d_in[6];
    const float* bh   = (const float*)d_in[7];
    const float* fc1w = (const float*)d_in[8];
    const float* fc1b = (const float*)d_in[9];
    const float* fc2w = (const float*)d_in[10];
    const float* fc2b = (const float*)d_in[11];
    float* out = (float*)d_out;

    const int n = out_size;
    const int ntiles = (n + NPB - 1) / NPB;

    prep_kernel<<<64, 256>>>(wz, wh, fc1w);

    cudaFuncSetAttribute(fused_kernel, cudaFuncAttributeMaxDynamicSharedMemorySize, SMEM_BYTES);
    int grid = ntiles < 444 ? ntiles : 444;    // 148 SMs x 3 CTAs
    fused_kernel<<<grid, NTHR, SMEM_BYTES>>>(x, bz, bh, fc1b, fc2w, fc2b, out, n, ntiles);
}

// round 15
// speedup vs baseline: 1.0837x; 1.0837x over previous
#include <cuda_runtime.h>
#include <cuda_fp16.h>

typedef unsigned int u32;
typedef unsigned short u16;

#define NFEAT 256
#define NPB   128          // nodes per tile (m32 per warp, 4 warps)
#define NTHR  128

// ---- smem layout (bytes) ----
#define W_STRIDE 528                        // 64 rows x (512B + 16B pad): ldmatrix conflict-free
#define OFF_WH   0
#define OFF_X    33792                      // X ring: 4 stages x (4 warps x 32 rows x 64B)
#define XSTAGE   8192
#define NSTAGE   4
#define OFF_FC   (OFF_X + NSTAGE * XSTAGE)  // 66560
#define FCQ   0
#define FW2   512
#define FB1   544
#define FBZ   576
#define FBH   608
#define FB2   640
#define SMEM_BYTES (OFF_FC + 642 * 4)       // 69128 -> 3 CTAs/SM (170-reg cap @128thr)

// W folded: [n=64][k=256] row-major fp16
__device__ __align__(16) u16 g_Wh[64 * 256];
// fc1 packed for B-fragments: fc1q[jp][i] = {lo: fc1[2jp][i], hi: fc1[2jp+1][i]} fp16
__device__ __align__(16) u32 g_fc1q[16 * 32];

// ---------------------------------------------------------------------------
// Prep: fold wc[j][k] = (wz[0]+wz[1]) | (wh[0]+wh[1]) (x-rows only; h0=0 kills
// the H half of the concat and the r-gate). Also pack fc1 into b-frag layout.
// ---------------------------------------------------------------------------
__global__ void prep_kernel(const float* __restrict__ wz, const float* __restrict__ wh,
                            const float* __restrict__ fc1w) {
    int idx = blockIdx.x * 256 + threadIdx.x;
    if (idx < 64 * 256) {
        int j = idx >> 8, k = idx & 255;
        const int D1 = 288 * 32;
        float wc = (j < 32) ? (wz[k * 32 + j] + wz[D1 + k * 32 + j])
                            : (wh[k * 32 + (j - 32)] + wh[D1 + k * 32 + (j - 32)]);
        __half h = __float2half_rn(wc);
        g_Wh[j * 256 + k] = *reinterpret_cast<u16*>(&h);
    }
    if (idx < 512) {
        int jp = idx >> 5, i = idx & 31;
        __half lo = __float2half_rn(fc1w[(2 * jp) * 32 + i]);
        __half hi = __float2half_rn(fc1w[(2 * jp + 1) * 32 + i]);
        g_fc1q[idx] = ((u32)*reinterpret_cast<u16*>(&hi) << 16) | *reinterpret_cast<u16*>(&lo);
    }
}

// ---------------------------------------------------------------------------
// helpers
// ---------------------------------------------------------------------------
__device__ __forceinline__ u32 s2u(const void* p) {
    u32 a;
    asm("{ .reg .u64 t; cvta.to.shared.u64 t, %1; cvt.u32.u64 %0, t; }" : "=r"(a) : "l"(p));
    return a;
}
__device__ __forceinline__ void ldsm4(u32 a, u32& r0, u32& r1, u32& r2, u32& r3) {
    asm volatile("ldmatrix.sync.aligned.m8n8.x4.shared.b16 {%0,%1,%2,%3}, [%4];"
                 : "=r"(r0), "=r"(r1), "=r"(r2), "=r"(r3) : "r"(a));
}
__device__ __forceinline__ void mma16816(float* c, const u32* a, u32 b0, u32 b1) {
    asm volatile("mma.sync.aligned.m16n8k16.row.col.f32.f16.f16.f32 "
                 "{%0,%1,%2,%3},{%4,%5,%6,%7},{%8,%9},{%0,%1,%2,%3};"
                 : "+f"(c[0]), "+f"(c[1]), "+f"(c[2]), "+f"(c[3])
                 : "r"(a[0]), "r"(a[1]), "r"(a[2]), "r"(a[3]), "r"(b0), "r"(b1));
}
__device__ __forceinline__ u32 packh(float lo, float hi) {  // reg = {hi16 | lo16}
    u32 r; asm("cvt.rn.f16x2.f32 %0, %1, %2;" : "=r"(r) : "f"(hi), "f"(lo)); return r;
}
__device__ __forceinline__ void cpasync16(u32 dst, const void* src) {
    asm volatile("cp.async.cg.shared.global [%0], [%1], 16;" :: "r"(dst), "l"(src));
}
__device__ __forceinline__ void cp_commit() {
    asm volatile("cp.async.commit_group;" ::: "memory");
}
__device__ __forceinline__ void cp_wait3() {
    asm volatile("cp.async.wait_group 3;" ::: "memory");
}
__device__ __forceinline__ float sigf(float x) { return 1.f / (1.f + __expf(-x)); }
__device__ __forceinline__ float tanhg(float x) {
    float e = __expf(-2.f * fabsf(x));
    return copysignf((1.f - e) / (1.f + e), x);
}
__device__ __forceinline__ float2 lds64(u32 a) {
    float2 v;
    asm volatile("ld.shared.v2.f32 {%0,%1}, [%2];" : "=f"(v.x), "=f"(v.y) : "r"(a));
    return v;
}

// ---------------------------------------------------------------------------
// Persistent fused kernel: 128 threads (4 warps x m32n64), 3 CTAs/SM.
// XOR-swizzled 4-deep cp.async ring; A-fragment fetch pipelined one chunk
// ahead; pipeline flows across tiles. Doubled m amortizes the per-chunk W
// ldmatrix reads (B smem traffic halved per delivered X byte). fp16 HMMA GEMM
// + register-resident GRU gates + tensor-core fc head.
// ---------------------------------------------------------------------------
__global__ void __launch_bounds__(NTHR, 3)
fused_kernel(const float* __restrict__ x,
             const float* __restrict__ bz, const float* __restrict__ bh,
             const float* __restrict__ fc1b,
             const float* __restrict__ fc2w, const float* __restrict__ fc2b,
             float* __restrict__ out, int n, int ntiles)
{
    extern __shared__ char sm[];
    const u32 sb = s2u(sm);
    const int tid  = threadIdx.x;
    const int wid  = tid >> 5;
    const int lane = tid & 31;
    const int g    = lane >> 2;        // row within 8-row group
    const int tg   = lane & 3;
    const int gs   = gridDim.x;
    const int s    = g & 3;            // swizzle key (rows g+8q share g&3)

    // cp.async write: lane (g,tg) writes its 16B unit tg at swizzled slot tg^s;
    // warp region = 32 rows x 64B = 2048B; row g+8q at +q*512
    const u32 xw = sb + OFF_X + (u32)wid * 2048 + (u32)g * 64 + (u32)((tg ^ s) << 4);
    // fragment reads (LDS.64) at swizzled addresses (validated R10-R14);
    // mi (0/1) selects rows g+16mi / g+8+16mi via +mi*1024 / +512
    const u32 ra0 = sb + OFF_X + (u32)wid * 2048 + (u32)g * 64
                  + (u32)((((tg >> 1) ^ s) << 4) + ((tg & 1) << 3));
    const u32 ra2 = sb + OFF_X + (u32)wid * 2048 + (u32)g * 64
                  + (u32)(((((tg >> 1) | 2) ^ s) << 4) + ((tg & 1) << 3));

    // per-tile source row pointers (rows g+8q of this warp's m32 slice), clamped
    const float* psC[4];
    auto mk_ps = [&](int tile) {
        #pragma unroll
        for (int q = 0; q < 4; q++) {
            int node = tile * NPB + wid * 32 + q * 8 + g;
            if (node > n - 1) node = n - 1;
            psC[q] = x + (size_t)node * NFEAT + tg * 4;
        }
    };
    const size_t tileStride = (size_t)gs * NPB * NFEAT;   // floats between my tiles

    int t = blockIdx.x;
    mk_ps(t);

    // ---- preamble: chunks 0..3 of first tile into stages 0..3 ----
    #pragma unroll
    for (int c = 0; c < NSTAGE; c++) {
        #pragma unroll
        for (int q = 0; q < 4; q++)
            cpasync16(xw + c * XSTAGE + q * 512, psC[q] + c * 16);
        cp_commit();
    }

    // ---- stage W into padded smem (once) ----
    {
        const uint4* sH = (const uint4*)g_Wh;
        #pragma unroll
        for (int it = 0; it < 16; it++) {
            int e = tid + 128 * it;           // 2048 uint4
            int row = e >> 5, c16 = e & 31;
            *(uint4*)(sm + OFF_WH + row * W_STRIDE + c16 * 16) = sH[e];
        }
    }
    // ---- stage fc head + biases (once) ----
    u32* FCq = (u32*)(sm + OFF_FC);
    float* FCf = (float*)(sm + OFF_FC);
    #pragma unroll
    for (int q = 0; q < 4; q++) FCq[FCQ + q * 128 + tid] = g_fc1q[q * 128 + tid];
    if (tid < 32) {
        FCf[FW2 + tid] = fc2w[tid];
        FCf[FB1 + tid] = fc1b[tid];
        FCf[FBZ + tid] = bz[tid];
        FCf[FBH + tid] = bh[tid];
    }
    if (tid == 0) FCf[FB2] = fc2b[0];

    // ldmatrix address for B (n16 x k16, x4), validated R3-R14
    const int rowB = (lane & 7) + ((lane >> 4) & 1) * 8;
    const u32 boff = (u32)rowB * W_STRIDE + (u32)((lane >> 3) & 1) * 16;

    // ---- pipeline setup: fetch chunk 0 fragments into A_cur ----
    u32 A_cur[2][4];
    cp_wait3();                // 4 preamble commits -> chunk 0 landed
    __syncwarp();
    #pragma unroll
    for (int mi = 0; mi < 2; mi++) {
        float2 d0 = lds64(ra0 + mi * 1024);
        float2 d1 = lds64(ra0 + mi * 1024 + 512);
        float2 d2 = lds64(ra2 + mi * 1024);
        float2 d3 = lds64(ra2 + mi * 1024 + 512);
        A_cur[mi][0] = packh(d0.x, d0.y);
        A_cur[mi][1] = packh(d1.x, d1.y);
        A_cur[mi][2] = packh(d2.x, d2.y);
        A_cur[mi][3] = packh(d3.x, d3.y);
    }

    __syncthreads();   // W/FC staged; the only CTA barrier

    // =========================== persistent tile loop ===========================
    while (t < ntiles) {
        const int tn = t + gs;
        const bool hasNext = (tn < ntiles);

        float acc[2][8][4];
        #pragma unroll
        for (int mi = 0; mi < 2; mi++)
            #pragma unroll
            for (int nt = 0; nt < 8; nt++)
                #pragma unroll
                for (int r = 0; r < 4; r++) acc[mi][nt][r] = 0.f;

        #pragma unroll
        for (int c = 0; c < 16; c++) {
            const int st = c & (NSTAGE - 1);

            // refill stage st: chunks 4..15 of this tile (iters 0..11), then
            // chunks 0..3 of my NEXT tile (iters 12..15, psC advanced in place)
            if (c == 12) {
                if (hasNext) {
                    if ((tn + 1) * NPB <= n) {        // fast path: no clamping
                        #pragma unroll
                        for (int q = 0; q < 4; q++) psC[q] += tileStride;
                    } else {
                        mk_ps(tn);                    // final partial tile
                    }
                }
            }
            if (c < 12) {
                #pragma unroll
                for (int q = 0; q < 4; q++)
                    cpasync16(xw + st * XSTAGE + q * 512, psC[q] + (c + 4) * 16);
            } else if (hasNext) {
                #pragma unroll
                for (int q = 0; q < 4; q++)
                    cpasync16(xw + st * XSTAGE + q * 512, psC[q] + (c - 12) * 16);
            }
            cp_commit();       // uniform group counting (empty groups OK)

            // B fragments + 16 HMMAs on the prefetched A_cur (chunk c)
            const u32 kb = (u32)c * 32;
            #pragma unroll
            for (int nq = 0; nq < 4; nq++) {
                u32 b0, b1, b2, b3;
                ldsm4(sb + OFF_WH + boff + nq * 16 * W_STRIDE + kb, b0, b1, b2, b3);
                mma16816(acc[0][2 * nq],     A_cur[0], b0, b1);
                mma16816(acc[0][2 * nq + 1], A_cur[0], b2, b3);
                mma16816(acc[1][2 * nq],     A_cur[1], b0, b1);
                mma16816(acc[1][2 * nq + 1], A_cur[1], b2, b3);
            }

            // fetch chunk c+1 fragments (c==15: next tile's chunk 0) for next iter
            cp_wait3();        // groups 0..c+1 complete
            __syncwarp();
            const int stn = (c + 1) & (NSTAGE - 1);
            #pragma unroll
            for (int mi = 0; mi < 2; mi++) {
                float2 d0 = lds64(ra0 + mi * 1024 + stn * XSTAGE);
                float2 d1 = lds64(ra0 + mi * 1024 + stn * XSTAGE + 512);
                float2 d2 = lds64(ra2 + mi * 1024 + stn * XSTAGE);
                float2 d3 = lds64(ra2 + mi * 1024 + stn * XSTAGE + 512);
                A_cur[mi][0] = packh(d0.x, d0.y);
                A_cur[mi][1] = packh(d1.x, d1.y);
                A_cur[mi][2] = packh(d2.x, d2.y);
                A_cur[mi][3] = packh(d3.x, d3.y);
            }
        }

        // ============== register-resident epilogue (R6/R7 m32 form, proven) ==============
        u32 Afc[2][2][4];
        #pragma unroll
        for (int mi = 0; mi < 2; mi++)
            #pragma unroll
            for (int c = 0; c < 2; c++)
                #pragma unroll
                for (int half = 0; half < 2; half++) {
                    int ntz = 2 * c + half;
                    float2 bzv = *(float2*)(FCf + FBZ + 8 * ntz + 2 * tg);
                    float2 bhv = *(float2*)(FCf + FBH + 8 * ntz + 2 * tg);
                    float h0 = (1.f - sigf(acc[mi][ntz][0] + bzv.x)) * tanhg(acc[mi][ntz + 4][0] + bhv.x);
                    float h1 = (1.f - sigf(acc[mi][ntz][1] + bzv.y)) * tanhg(acc[mi][ntz + 4][1] + bhv.y);
                    float h2 = (1.f - sigf(acc[mi][ntz][2] + bzv.x)) * tanhg(acc[mi][ntz + 4][2] + bhv.x);
                    float h3 = (1.f - sigf(acc[mi][ntz][3] + bzv.y)) * tanhg(acc[mi][ntz + 4][3] + bhv.y);
                    Afc[mi][c][half * 2 + 0] = packh(h0, h1);
                    Afc[mi][c][half * 2 + 1] = packh(h2, h3);
                }

        float a2[2][4][4];
        #pragma unroll
        for (int q = 0; q < 4; q++) {
            float2 b1v = *(float2*)(FCf + FB1 + 8 * q + 2 * tg);
            #pragma unroll
            for (int mi = 0; mi < 2; mi++) {
                a2[mi][q][0] = b1v.x; a2[mi][q][1] = b1v.y;
                a2[mi][q][2] = b1v.x; a2[mi][q][3] = b1v.y;
            }
        }
        #pragma unroll
        for (int c = 0; c < 2; c++)
            #pragma unroll
            for (int q = 0; q < 4; q++) {
                u32 bf0 = FCq[FCQ + (tg + 8 * c) * 32 + g + 8 * q];
                u32 bf1 = FCq[FCQ + (tg + 4 + 8 * c) * 32 + g + 8 * q];
                mma16816(a2[0][q], Afc[0][c], bf0, bf1);
                mma16816(a2[1][q], Afc[1][c], bf0, bf1);
            }

        const float b2 = FCf[FB2];
        #pragma unroll
        for (int mi = 0; mi < 2; mi++) {
            float og = 0.f, og8 = 0.f;
            #pragma unroll
            for (int q = 0; q < 4; q++) {
                float2 w2 = *(float2*)(FCf + FW2 + 8 * q + 2 * tg);
                og  = fmaf(fmaxf(a2[mi][q][0], 0.f), w2.x, og);
                og  = fmaf(fmaxf(a2[mi][q][1], 0.f), w2.y, og);
                og8 = fmaf(fmaxf(a2[mi][q][2], 0.f), w2.x, og8);
                og8 = fmaf(fmaxf(a2[mi][q][3], 0.f), w2.y, og8);
            }
            og  += __shfl_xor_sync(0xffffffffu, og, 1);
            og  += __shfl_xor_sync(0xffffffffu, og, 2);
            og8 += __shfl_xor_sync(0xffffffffu, og8, 1);
            og8 += __shfl_xor_sync(0xffffffffu, og8, 2);
            if (tg == 0) {
                int node = t * NPB + wid * 32 + mi * 16 + g;
                if (node < n)     out[node]     = sigf(og + b2);
                if (node + 8 < n) out[node + 8] = sigf(og8 + b2);
            }
        }

        t = tn;
    }
}

// ---------------------------------------------------------------------------
// Launch. Inputs: x, edge_index(dead), w_z, b_z, w_r(dead), b_r(dead),
// w_h, b_h, fc1_w, fc1_b, fc2_w, fc2_b. Output: [N,1] float.
// ---------------------------------------------------------------------------
extern "C" void kernel_launch(void* const* d_in, const int* in_sizes, int n_in,
                              void* d_out, int out_size) {
    const float* x    = (const float*)d_in[0];
    const float* wz   = (const float*)d_in[2];
    const float* bz   = (const float*)d_in[3];
    const float* wh   = (const float*)d_in[6];
    const float* bh   = (const float*)d_in[7];
    const float* fc1w = (const float*)d_in[8];
    const float* fc1b = (const float*)d_in[9];
    const float* fc2w = (const float*)d_in[10];
    const float* fc2b = (const float*)d_in[11];
    float* out = (float*)d_out;

    const int n = out_size;
    const int ntiles = (n + NPB - 1) / NPB;

    prep_kernel<<<64, 256>>>(wz, wh, fc1w);

    cudaFuncSetAttribute(fused_kernel, cudaFuncAttributeMaxDynamicSharedMemorySize, SMEM_BYTES);
    int grid = ntiles < 444 ? ntiles : 444;    // 148 SMs x 3 CTAs
    fused_kernel<<<grid, NTHR, SMEM_BYTES>>>(x, bz, bh, fc1b, fc2w, fc2b, out, n, ntiles);
}